// round 2
// baseline (speedup 1.0000x reference)
#include <cuda_runtime.h>
#include <limits.h>
#include <math.h>

#define NMAX 40000
#define EMAX 320000
#define D 128
#define PEK 73

// ---------------- scratch (device globals; no allocations allowed) ----------
__device__ float g_x[NMAX * D];
__device__ float g_q[NMAX * D];
__device__ float g_k[NMAX * D];
__device__ float g_v[NMAX * D];
__device__ float g_s[NMAX * D];
__device__ float g_agg[NMAX * D];
__device__ float g_den[NMAX * 4];
__device__ int   g_m[NMAX * 4];
__device__ float g_pe[EMAX * PEK];
__device__ float g_e[(size_t)EMAX * D];
__device__ float g_score[EMAX * 4];
__device__ int   g_nid64;   // 1 if n_id is int64
__device__ int   g_ei64;    // 1 if edge_index is int64

// ordered-int encoding for float atomicMax
__device__ __forceinline__ int fkey(float f) {
    int x = __float_as_int(f);
    return x < 0 ? (x ^ 0x7fffffff) : x;
}
__device__ __forceinline__ float fdecode(int k) {
    int x = k < 0 ? (k ^ 0x7fffffff) : k;
    return __int_as_float(x);
}

__device__ __forceinline__ int ld_idx(const void* p, long long i, int is64) {
    return is64 ? (int)((const long long*)p)[i] : ((const int*)p)[i];
}

// ---------------- index dtype detection (odd 32-bit words all zero => int64)
__global__ void k_detect_nid(const int* __restrict__ p) {
    int v = p[1 + 2 * threadIdx.x];             // words 1,3,...,2047 (N=40000 > 2048)
    int any = __syncthreads_or(v != 0);
    if (threadIdx.x == 0) g_nid64 = (any == 0) ? 1 : 0;
}
__global__ void k_detect_ei(const int* __restrict__ p) {
    int v = p[1 + 2 * threadIdx.x];
    int any = __syncthreads_or(v != 0);
    if (threadIdx.x == 0) g_ei64 = (any == 0) ? 1 : 0;
}

// ---------------- gather x = memory_table[n_id] -----------------------------
__global__ void k_gather(const float* __restrict__ mem, const void* __restrict__ n_id, int N) {
    int idx = blockIdx.x * blockDim.x + threadIdx.x;
    if (idx >= N * 32) return;
    int i = idx >> 5, c4 = idx & 31;
    int node = ld_idx(n_id, i, g_nid64);
    float4 v = ((const float4*)(mem + (size_t)node * D))[c4];
    ((float4*)(g_x + (size_t)i * D))[c4] = v;
}

// ---------------- pe = concat(ea[:, :3], ea[:, 4:66], et_emb[etype]) --------
__global__ void k_prep_pe(const float* __restrict__ ea, const float* __restrict__ et, int E) {
    int idx = blockIdx.x * blockDim.x + threadIdx.x;
    if (idx >= E * PEK) return;
    int e = idx / PEK, k = idx - e * PEK;
    float val;
    if (k < 3) {
        val = ea[e * 66 + k];
    } else if (k < 65) {
        val = ea[e * 66 + k + 1];
    } else {
        int t = (int)ea[e * 66 + 3];
        val = et[t * 8 + (k - 65)];
    }
    g_pe[idx] = val;
}

// ---------------- fused node GEMM: q,k,v,s = g_x @ {Wq,Wk,Wv,Ws} + b --------
// A is ALWAYS g_x (referenced in device code; never pass __device__ symbols
// from host). BM=64, BN=128, BK=32; 256 threads; 8 rows x 4 cols per thread.
__global__ __launch_bounds__(256) void k_node_gemm4(
    const float* __restrict__ Wq, const float* __restrict__ Wk,
    const float* __restrict__ Wv, const float* __restrict__ Ws,
    const float* __restrict__ bq, const float* __restrict__ bk,
    const float* __restrict__ bv, const float* __restrict__ bs,
    int M)
{
    __shared__ float As[64][128];   // full K resident
    __shared__ float Bs[32][128];   // one K-chunk of the weight

    int row0 = blockIdx.x * 64;
    int tid = threadIdx.x;

    // load A tile (64x128) as float4s, linear
    {
        const float4* A4 = (const float4*)(g_x + (size_t)row0 * D);
        float4* As4 = (float4*)&As[0][0];
        for (int i = tid; i < 64 * 32; i += 256) {
            int r = i >> 5;
            if (row0 + r < M) As4[i] = A4[i];
            else              As4[i] = make_float4(0.f, 0.f, 0.f, 0.f);
        }
    }
    __syncthreads();

    const float* Wp[4] = {Wq, Wk, Wv, Ws};
    const float* bp[4] = {bq, bk, bv, bs};
    float* Cp[4] = {g_q, g_k, g_v, g_s};

    int colg = tid & 31;   // *4 -> output column
    int rowg = tid >> 5;   // *8 -> output row base

    for (int w = 0; w < 4; w++) {
        float acc[8][4];
        float4 bias = ((const float4*)bp[w])[colg];
#pragma unroll
        for (int i = 0; i < 8; i++) {
            acc[i][0] = bias.x; acc[i][1] = bias.y; acc[i][2] = bias.z; acc[i][3] = bias.w;
        }
        for (int k0 = 0; k0 < 128; k0 += 32) {
            __syncthreads();
            {
                const float4* W4 = (const float4*)(Wp[w] + (size_t)k0 * D);
                float4* Bs4 = (float4*)&Bs[0][0];
                for (int i = tid; i < 32 * 32; i += 256) Bs4[i] = W4[i];
            }
            __syncthreads();
#pragma unroll
            for (int k = 0; k < 32; k++) {
                float4 b = ((const float4*)&Bs[k][0])[colg];
#pragma unroll
                for (int i = 0; i < 8; i++) {
                    float a = As[rowg * 8 + i][k0 + k];
                    acc[i][0] += a * b.x;
                    acc[i][1] += a * b.y;
                    acc[i][2] += a * b.z;
                    acc[i][3] += a * b.w;
                }
            }
        }
#pragma unroll
        for (int i = 0; i < 8; i++) {
            int r = row0 + rowg * 8 + i;
            if (r < M) {
                float4 o = make_float4(acc[i][0], acc[i][1], acc[i][2], acc[i][3]);
                ((float4*)(Cp[w] + (size_t)r * D))[colg] = o;
            }
        }
    }
}

// ---------------- edge GEMM: e = pe[E,73] @ We[73,128] ----------------------
__global__ __launch_bounds__(256) void k_edge_gemm(const float* __restrict__ We, int E) {
    __shared__ float As[32][76];   // 32 edges x 73 (padded)
    __shared__ float Bs[PEK][128];

    int e0 = blockIdx.x * 32;
    int tid = threadIdx.x;

    for (int i = tid; i < 32 * PEK; i += 256) {
        int r = i / PEK, k = i - r * PEK;
        As[r][k] = (e0 + r < E) ? g_pe[(size_t)(e0 + r) * PEK + k] : 0.f;
    }
    {
        float4* Bs4 = (float4*)&Bs[0][0];
        const float4* W4 = (const float4*)We;
        for (int i = tid; i < PEK * 32; i += 256) Bs4[i] = W4[i];
    }
    __syncthreads();

    int colg = tid & 31;   // *4
    int rowg = tid >> 5;   // *4
    float acc[4][4];
#pragma unroll
    for (int i = 0; i < 4; i++)
        for (int j = 0; j < 4; j++) acc[i][j] = 0.f;

    for (int k = 0; k < PEK; k++) {
        float4 b = ((const float4*)&Bs[k][0])[colg];
#pragma unroll
        for (int i = 0; i < 4; i++) {
            float a = As[rowg * 4 + i][k];
            acc[i][0] += a * b.x;
            acc[i][1] += a * b.y;
            acc[i][2] += a * b.z;
            acc[i][3] += a * b.w;
        }
    }
#pragma unroll
    for (int i = 0; i < 4; i++) {
        int r = e0 + rowg * 4 + i;
        if (r < E) {
            float4 o = make_float4(acc[i][0], acc[i][1], acc[i][2], acc[i][3]);
            ((float4*)(g_e + (size_t)r * D))[colg] = o;
        }
    }
}

// ---------------- per-layer init: agg=0, den=0, m=-inf ----------------------
__global__ void k_init(int N) {
    int idx = blockIdx.x * blockDim.x + threadIdx.x;
    if (idx < N * D) g_agg[idx] = 0.f;
    if (idx < N * 4) { g_den[idx] = 0.f; g_m[idx] = INT_MIN; }
}

// ---------------- scores + segment max (warp per edge) ----------------------
__global__ void k_score(const void* __restrict__ ei, int E) {
    int gt = blockIdx.x * blockDim.x + threadIdx.x;
    int ed = gt >> 5;
    if (ed >= E) return;
    int lane = gt & 31;
    int is64 = g_ei64;
    int src = ld_idx(ei, ed, is64);
    int dst = ld_idx(ei, (long long)E + ed, is64);
    float4 q  = ((const float4*)(g_q + (size_t)dst * D))[lane];
    float4 kk = ((const float4*)(g_k + (size_t)src * D))[lane];
    float4 ev = ((const float4*)(g_e + (size_t)ed  * D))[lane];
    float s = q.x * (kk.x + ev.x) + q.y * (kk.y + ev.y)
            + q.z * (kk.z + ev.z) + q.w * (kk.w + ev.w);
    s += __shfl_xor_sync(0xffffffffu, s, 1);
    s += __shfl_xor_sync(0xffffffffu, s, 2);
    s += __shfl_xor_sync(0xffffffffu, s, 4);
    if ((lane & 7) == 0) {
        int h = lane >> 3;
        float sc = s * 0.1767766953f;  // 1/sqrt(32)
        g_score[ed * 4 + h] = sc;
        atomicMax(&g_m[dst * 4 + h], fkey(sc));
    }
}

// ---------------- exp(score - m) + segment denom ----------------------------
__global__ void k_ex(const void* __restrict__ ei, int E) {
    int idx = blockIdx.x * blockDim.x + threadIdx.x;
    if (idx >= E * 4) return;
    int ed = idx >> 2, h = idx & 3;
    int dst = ld_idx(ei, (long long)E + ed, g_ei64);
    float mm = fdecode(g_m[dst * 4 + h]);
    float ex = expf(g_score[idx] - mm);
    g_score[idx] = ex;
    atomicAdd(&g_den[dst * 4 + h], ex);
}

// ---------------- weighted scatter-add of v ---------------------------------
__global__ void k_agg(const void* __restrict__ ei, int E) {
    int idx = blockIdx.x * blockDim.x + threadIdx.x;
    if (idx >= E * 32) return;
    int ed = idx >> 5, c4 = idx & 31;
    int is64 = g_ei64;
    int src = ld_idx(ei, ed, is64);
    int dst = ld_idx(ei, (long long)E + ed, is64);
    int h = c4 >> 3;
    float alpha = g_score[ed * 4 + h] / (g_den[dst * 4 + h] + 1e-16f);
    float4 v  = ((const float4*)(g_v + (size_t)src * D))[c4];
    float4 ev = ((const float4*)(g_e + (size_t)ed  * D))[c4];
    float* a = g_agg + (size_t)dst * D + c4 * 4;
    atomicAdd(a + 0, (v.x + ev.x) * alpha);
    atomicAdd(a + 1, (v.y + ev.y) * alpha);
    atomicAdd(a + 2, (v.z + ev.z) * alpha);
    atomicAdd(a + 3, (v.w + ev.w) * alpha);
}

// ---------------- out = agg + skip (+relu); relu -> g_x, else -> out --------
__global__ void k_final(float* __restrict__ out, int N, int relu) {
    int idx = blockIdx.x * blockDim.x + threadIdx.x;
    if (idx >= N * 32) return;
    int i = idx >> 5, c4 = idx & 31;
    float4 a = ((const float4*)(g_agg + (size_t)i * D))[c4];
    float4 s = ((const float4*)(g_s + (size_t)i * D))[c4];
    float4 o = make_float4(a.x + s.x, a.y + s.y, a.z + s.z, a.w + s.w);
    if (relu) {
        o.x = fmaxf(o.x, 0.f); o.y = fmaxf(o.y, 0.f);
        o.z = fmaxf(o.z, 0.f); o.w = fmaxf(o.w, 0.f);
        ((float4*)(g_x + (size_t)i * D))[c4] = o;
    } else {
        ((float4*)(out + (size_t)i * D))[c4] = o;
    }
}

// ---------------- launch -----------------------------------------------------
extern "C" void kernel_launch(void* const* d_in, const int* in_sizes, int n_in,
                              void* d_out, int out_size) {
    const float* mem    = (const float*)d_in[0];
    const float* ea     = (const float*)d_in[1];
    const float* et_emb = (const float*)d_in[2];
    const float* W1[5]  = {(const float*)d_in[3], (const float*)d_in[4], (const float*)d_in[5],
                           (const float*)d_in[6], (const float*)d_in[7]};   // Wq,Wk,Wv,We,Ws
    const float* b1[4]  = {(const float*)d_in[8], (const float*)d_in[9],
                           (const float*)d_in[10], (const float*)d_in[11]}; // bq,bk,bv,bs
    const float* W2[5]  = {(const float*)d_in[12], (const float*)d_in[13], (const float*)d_in[14],
                           (const float*)d_in[15], (const float*)d_in[16]};
    const float* b2[4]  = {(const float*)d_in[17], (const float*)d_in[18],
                           (const float*)d_in[19], (const float*)d_in[20]};
    const void* n_id = d_in[21];
    const void* ei   = d_in[22];
    float* out = (float*)d_out;

    int N = in_sizes[21];
    int E = in_sizes[22] / 2;
    if (N > NMAX) N = NMAX;
    if (E > EMAX) E = EMAX;

    const int T = 256;
    k_detect_nid<<<1, 1024>>>((const int*)n_id);
    k_detect_ei<<<1, 1024>>>((const int*)ei);
    k_gather<<<(N * 32 + T - 1) / T, T>>>(mem, n_id, N);
    k_prep_pe<<<(E * PEK + T - 1) / T, T>>>(ea, et_emb, E);

    // ---- layer 1 ----
    k_node_gemm4<<<(N + 63) / 64, 256>>>(W1[0], W1[1], W1[2], W1[4],
                                         b1[0], b1[1], b1[2], b1[3], N);
    k_edge_gemm<<<(E + 31) / 32, 256>>>(W1[3], E);
    k_init<<<(N * D + T - 1) / T, T>>>(N);
    k_score<<<(E * 32 + T - 1) / T, T>>>(ei, E);
    k_ex<<<(E * 4 + T - 1) / T, T>>>(ei, E);
    k_agg<<<(E * 32 + T - 1) / T, T>>>(ei, E);
    k_final<<<(N * 32 + T - 1) / T, T>>>(out, N, 1);   // relu -> g_x

    // ---- layer 2 ----
    k_node_gemm4<<<(N + 63) / 64, 256>>>(W2[0], W2[1], W2[2], W2[4],
                                         b2[0], b2[1], b2[2], b2[3], N);
    k_edge_gemm<<<(E + 31) / 32, 256>>>(W2[3], E);
    k_init<<<(N * D + T - 1) / T, T>>>(N);
    k_score<<<(E * 32 + T - 1) / T, T>>>(ei, E);
    k_ex<<<(E * 4 + T - 1) / T, T>>>(ei, E);
    k_agg<<<(E * 32 + T - 1) / T, T>>>(ei, E);
    k_final<<<(N * 32 + T - 1) / T, T>>>(out, N, 0);   // -> d_out
}